// round 5
// baseline (speedup 1.0000x reference)
#include <cuda_runtime.h>
#include <cstdint>

#define IN_DIM   64
#define HID      128
#define HID2     256
#define OUT_DIM  64
#define NSTEPS   20
#define NTHREADS 256
#define M_TILE   64
#define AS       260   // A-buffer row stride (floats): 4*r+k conflict-free
#define HS       132   // h-buffer row stride
#define WSTR     264   // W-stage row stride: 8*k+n conflict-free
#define KCH      32    // K chunk per stage

static constexpr float DTC = 1.0f / 20.0f;

// Pre-rounded (TF32-RN) weights; __device__ globals = sanctioned scratch.
__device__ float g_Wenc[IN_DIM * HID];
__device__ float g_W1[HID * HID2];
__device__ float g_W2[HID2 * HID2];
__device__ float g_W3[HID2 * HID];
__device__ float g_Wdec[HID * OUT_DIM];

__device__ __forceinline__ float tf32r(float x) {
    uint32_t u;
    asm("cvt.rna.tf32.f32 %0, %1;" : "=r"(u) : "f"(x));
    return __uint_as_float(u);
}

// tanh(x) = 1 - 2/(e^{2x}+1); exact formula, MUFU-approx ex2/rcp (~1e-6 err).
// Saturates correctly at +/-1 for large |x| (inf/0 handled by rcp.approx).
__device__ __forceinline__ float fast_tanh(float x) {
    float e;
    asm("ex2.approx.f32 %0, %1;" : "=f"(e) : "f"(x * 2.88539008177792681472f));
    float r;
    asm("rcp.approx.f32 %0, %1;" : "=f"(r) : "f"(e + 1.0f));
    return fmaf(-2.0f, r, 1.0f);
}

__device__ __forceinline__ void mma8(float c[4], uint32_t a0, uint32_t a1,
                                     uint32_t a2, uint32_t a3,
                                     uint32_t b0, uint32_t b1) {
    asm("mma.sync.aligned.m16n8k8.row.col.f32.tf32.tf32.f32 "
        "{%0,%1,%2,%3},{%4,%5,%6,%7},{%8,%9},{%0,%1,%2,%3};"
        : "+f"(c[0]), "+f"(c[1]), "+f"(c[2]), "+f"(c[3])
        : "r"(a0), "r"(a1), "r"(a2), "r"(a3), "r"(b0), "r"(b1));
}

__device__ __forceinline__ void cp16(uint32_t saddr, const float* g) {
    asm volatile("cp.async.cg.shared.global [%0], [%1], 16;" ::"r"(saddr), "l"(g));
}
__device__ __forceinline__ void cpcommit() {
    asm volatile("cp.async.commit_group;" ::: "memory");
}
template <int P>
__device__ __forceinline__ void cpwait() {
    asm volatile("cp.async.wait_group %0;" ::"n"(P) : "memory");
}

// Stage KCH rows of W (K x N, row-major) into a SMEM slot with WSTR stride.
template <int N>
__device__ __forceinline__ void stageW(float* slot, const float* Wg, int kbase) {
    uint32_t sb = (uint32_t)__cvta_generic_to_shared(slot);
    constexpr int OPS = KCH * (N / 4);  // 16B ops
#pragma unroll
    for (int o = 0; o < OPS / NTHREADS; o++) {
        int idx = o * NTHREADS + (int)threadIdx.x;
        int r = idx / (N / 4);
        int s = idx % (N / 4);
        cp16(sb + (uint32_t)(r * WSTR + s * 4) * 4u, Wg + (kbase + r) * N + s * 4);
    }
}

// C[2][NF][4] = A(64 x K, SMEM Ab) * W(K x N, global pre-rounded), warp tile 32 x N/4.
// Warp grid: 2 (M) x 4 (N). All barriers uniform across the CTA.
template <int K, int N>
__device__ __forceinline__ void gemm_core(const float* __restrict__ Wg,
                                          const float* __restrict__ Ab,
                                          float* __restrict__ Wb,
                                          float C[2][8][4], int m0, int n0,
                                          int g, int t) {
    constexpr int NF = (N / 4) / 8;
#pragma unroll
    for (int mi = 0; mi < 2; mi++)
#pragma unroll
        for (int j = 0; j < NF; j++)
#pragma unroll
            for (int e = 0; e < 4; e++) C[mi][j][e] = 0.0f;

    constexpr int NCH = K / KCH;
    stageW<N>(Wb, Wg, 0);
    cpcommit();
#pragma unroll 1
    for (int ch = 0; ch < NCH; ch++) {
        if (ch + 1 < NCH) {
            stageW<N>(Wb + ((ch + 1) & 1) * (KCH * WSTR), Wg, (ch + 1) * KCH);
            cpcommit();
            cpwait<1>();
        } else {
            cpwait<0>();
        }
        __syncthreads();  // staged chunk visible; also orders prior epilogue writes to Ab
        const float* W = Wb + (ch & 1) * (KCH * WSTR);
#pragma unroll
        for (int k8 = 0; k8 < KCH / 8; k8++) {
            const int ka = ch * KCH + k8 * 8;
            uint32_t a[2][4];
#pragma unroll
            for (int mi = 0; mi < 2; mi++) {
                const float* Ar0 = Ab + (m0 + mi * 16 + g) * AS + ka;
                const float* Ar1 = Ab + (m0 + mi * 16 + g + 8) * AS + ka;
                a[mi][0] = __float_as_uint(Ar0[t]);
                a[mi][1] = __float_as_uint(Ar1[t]);
                a[mi][2] = __float_as_uint(Ar0[t + 4]);
                a[mi][3] = __float_as_uint(Ar1[t + 4]);
            }
            const float* Wk = W + (k8 * 8) * WSTR;
#pragma unroll
            for (int j = 0; j < NF; j++) {
                uint32_t b0 = __float_as_uint(Wk[t * WSTR + n0 + j * 8 + g]);
                uint32_t b1 = __float_as_uint(Wk[(t + 4) * WSTR + n0 + j * 8 + g]);
                mma8(C[0][j], a[0][0], a[0][1], a[0][2], a[0][3], b0, b1);
                mma8(C[1][j], a[1][0], a[1][1], a[1][2], a[1][3], b0, b1);
            }
        }
        __syncthreads();  // all warps done reading before buffer/Ab reuse
    }
}

__global__ void prep_kernel(const float* We, const float* W1, const float* W2,
                            const float* W3, const float* Wd) {
    int i = blockIdx.x * NTHREADS + threadIdx.x;
    if (i < IN_DIM * HID) g_Wenc[i] = tf32r(We[i]);
    if (i < HID * HID2) g_W1[i] = tf32r(W1[i]);
    if (i < HID2 * HID2) g_W2[i] = tf32r(W2[i]);
    if (i < HID2 * HID) g_W3[i] = tf32r(W3[i]);
    if (i < HID * OUT_DIM) g_Wdec[i] = tf32r(Wd[i]);
}

__global__ void __launch_bounds__(NTHREADS, 1)
node_kernel(const float* __restrict__ x, const float* __restrict__ benc,
            const float* __restrict__ b1, const float* __restrict__ b2,
            const float* __restrict__ b3, const float* __restrict__ bdec,
            float* __restrict__ out) {
    extern __shared__ float smem[];
    float* Ab = smem;                   // [64][AS]  activations (tf32-rounded)
    float* Hb = Ab + M_TILE * AS;       // [64][HS]  h state (full fp32)
    float* Wb = Hb + M_TILE * HS;       // [2][KCH][WSTR] weight stage
    float* Bs = Wb + 2 * KCH * WSTR;    // biases: b1[0:256) b2[256:512) b3[512:640) benc[640:768) bdec[768:832)

    const int tid = threadIdx.x;
    Bs[tid] = b1[tid];
    Bs[256 + tid] = b2[tid];
    if (tid < 128) {
        Bs[512 + tid] = b3[tid];
        Bs[640 + tid] = benc[tid];
    }
    if (tid < 64) Bs[768 + tid] = bdec[tid];

    const int row0 = blockIdx.x * M_TILE;
#pragma unroll 4
    for (int i = tid; i < M_TILE * IN_DIM; i += NTHREADS) {
        int r = i >> 6, c = i & 63;
        Ab[r * AS + c] = tf32r(x[(row0 + r) * IN_DIM + c]);
    }
    // gemm_core's first barrier (after cp.async wait) publishes Ab/Bs to all warps.

    const int warp = tid >> 5, lane = tid & 31;
    const int mw = warp >> 2, nwp = warp & 3;
    const int g = lane >> 2, t = lane & 3;
    const int m0 = mw * 32;

    float C[2][8][4];
    float acc[2][4][4];

    // ---- encoder: tanh(x @ Wenc + benc) -> Hb, Ab ----
    {
        const int n0 = nwp * 32;  // NF = 4
        gemm_core<IN_DIM, HID>(g_Wenc, Ab, Wb, C, m0, n0, g, t);
#pragma unroll
        for (int mi = 0; mi < 2; mi++)
#pragma unroll
            for (int j = 0; j < 4; j++)
#pragma unroll
                for (int e = 0; e < 4; e++) {
                    int rr = m0 + mi * 16 + g + ((e >> 1) << 3);
                    int cc = n0 + j * 8 + 2 * t + (e & 1);
                    float v = fast_tanh(C[mi][j][e] + Bs[640 + cc]);
                    Hb[rr * HS + cc] = v;
                    Ab[rr * AS + cc] = tf32r(v);
                }
    }

#pragma unroll 1
    for (int step = 0; step < NSTEPS; step++) {
#pragma unroll 1
        for (int ev = 0; ev < 4; ev++) {
            // GEMM1: tanh(htmp @ W1 + b1) -> Ab[:, 0:256)
            {
                const int n0 = nwp * 64;  // NF = 8
                gemm_core<HID, HID2>(g_W1, Ab, Wb, C, m0, n0, g, t);
#pragma unroll
                for (int mi = 0; mi < 2; mi++)
#pragma unroll
                    for (int j = 0; j < 8; j++)
#pragma unroll
                        for (int e = 0; e < 4; e++) {
                            int rr = m0 + mi * 16 + g + ((e >> 1) << 3);
                            int cc = n0 + j * 8 + 2 * t + (e & 1);
                            Ab[rr * AS + cc] = tf32r(fast_tanh(C[mi][j][e] + Bs[cc]));
                        }
            }
            // GEMM2: tanh(z1 @ W2 + b2) -> Ab
            {
                const int n0 = nwp * 64;  // NF = 8
                gemm_core<HID2, HID2>(g_W2, Ab, Wb, C, m0, n0, g, t);
#pragma unroll
                for (int mi = 0; mi < 2; mi++)
#pragma unroll
                    for (int j = 0; j < 8; j++)
#pragma unroll
                        for (int e = 0; e < 4; e++) {
                            int rr = m0 + mi * 16 + g + ((e >> 1) << 3);
                            int cc = n0 + j * 8 + 2 * t + (e & 1);
                            Ab[rr * AS + cc] = tf32r(fast_tanh(C[mi][j][e] + Bs[256 + cc]));
                        }
            }
            // GEMM3: k = z2 @ W3 + b3 ; RK4 bookkeeping -> Ab[:, 0:128), Hb
            {
                const int n0 = nwp * 32;  // NF = 4
                gemm_core<HID2, HID>(g_W3, Ab, Wb, C, m0, n0, g, t);
#pragma unroll
                for (int mi = 0; mi < 2; mi++)
#pragma unroll
                    for (int j = 0; j < 4; j++)
#pragma unroll
                        for (int e = 0; e < 4; e++) {
                            int rr = m0 + mi * 16 + g + ((e >> 1) << 3);
                            int cc = n0 + j * 8 + 2 * t + (e & 1);
                            float kv = C[mi][j][e] + Bs[512 + cc];
                            float h = Hb[rr * HS + cc];
                            if (ev == 0) {
                                acc[mi][j][e] = kv;
                                Ab[rr * AS + cc] = tf32r(fmaf(0.5f * DTC, kv, h));
                            } else if (ev == 1) {
                                acc[mi][j][e] += 2.0f * kv;
                                Ab[rr * AS + cc] = tf32r(fmaf(0.5f * DTC, kv, h));
                            } else if (ev == 2) {
                                acc[mi][j][e] += 2.0f * kv;
                                Ab[rr * AS + cc] = tf32r(fmaf(DTC, kv, h));
                            } else {
                                float hn = fmaf(DTC / 6.0f, acc[mi][j][e] + kv, h);
                                Hb[rr * HS + cc] = hn;
                                Ab[rr * AS + cc] = tf32r(hn);
                            }
                        }
            }
        }
    }

    // ---- decoder: hT @ Wdec + bdec -> out ----
    {
        const int n0 = nwp * 16;  // NF = 2
        gemm_core<HID, OUT_DIM>(g_Wdec, Ab, Wb, C, m0, n0, g, t);
#pragma unroll
        for (int mi = 0; mi < 2; mi++)
#pragma unroll
            for (int j = 0; j < 2; j++)
#pragma unroll
                for (int e = 0; e < 4; e++) {
                    int rr = m0 + mi * 16 + g + ((e >> 1) << 3);
                    int cc = n0 + j * 8 + 2 * t + (e & 1);
                    out[(size_t)(row0 + rr) * OUT_DIM + cc] = C[mi][j][e] + Bs[768 + cc];
                }
    }
}

static constexpr int SMEM_BYTES =
    (M_TILE * AS + M_TILE * HS + 2 * KCH * WSTR + 832) * 4;  // 171,264 B

extern "C" void kernel_launch(void* const* d_in, const int* in_sizes, int n_in,
                              void* d_out, int out_size) {
    const float* x    = (const float*)d_in[0];
    const float* Wenc = (const float*)d_in[1];
    const float* benc = (const float*)d_in[2];
    const float* W1   = (const float*)d_in[3];
    const float* b1   = (const float*)d_in[4];
    const float* W2   = (const float*)d_in[5];
    const float* b2   = (const float*)d_in[6];
    const float* W3   = (const float*)d_in[7];
    const float* b3   = (const float*)d_in[8];
    const float* Wdec = (const float*)d_in[9];
    const float* bdec = (const float*)d_in[10];
    float* out = (float*)d_out;

    const int batch = in_sizes[0] / IN_DIM;        // 65536
    const int grid  = batch / M_TILE;              // 1024

    cudaFuncSetAttribute(node_kernel, cudaFuncAttributeMaxDynamicSharedMemorySize,
                         SMEM_BYTES);

    // Pre-round weights to TF32 (RN) into __device__ scratch; covers max 65536 elems.
    prep_kernel<<<256, NTHREADS>>>(Wenc, W1, W2, W3, Wdec);
    node_kernel<<<grid, NTHREADS, SMEM_BYTES>>>(x, benc, b1, b2, b3, bdec, out);
}

// round 6
// speedup vs baseline: 1.0069x; 1.0069x over previous
#include <cuda_runtime.h>
#include <cstdint>

#define IN_DIM   64
#define HID      128
#define HID2     256
#define OUT_DIM  64
#define NSTEPS   20
#define NTHREADS 512
#define M_TILE   64
#define AS       260   // A-buffer row stride (floats): bank = 4g+t distinct mod 32
#define HS       132   // acc-buffer row stride
#define WSTR     264   // W-stage row stride: 8k+n conflict-free
#define KCH      32    // K chunk per stage
#define NSLOT    3     // weight pipeline depth

static constexpr float DTC = 1.0f / 20.0f;

// Pre-rounded (TF32-RN) weights; __device__ globals = sanctioned scratch.
__device__ float g_Wenc[IN_DIM * HID];
__device__ float g_W1[HID * HID2];
__device__ float g_W2[HID2 * HID2];
__device__ float g_W3[HID2 * HID];
__device__ float g_Wdec[HID * OUT_DIM];

__device__ __forceinline__ float tf32r(float x) {
    uint32_t u;
    asm("cvt.rna.tf32.f32 %0, %1;" : "=r"(u) : "f"(x));
    return __uint_as_float(u);
}

// tanh(x) = 1 - 2/(e^{2x}+1); MUFU ex2/rcp (~1e-6 err), saturates correctly.
__device__ __forceinline__ float fast_tanh(float x) {
    float e;
    asm("ex2.approx.f32 %0, %1;" : "=f"(e) : "f"(x * 2.88539008177792681472f));
    float r;
    asm("rcp.approx.f32 %0, %1;" : "=f"(r) : "f"(e + 1.0f));
    return fmaf(-2.0f, r, 1.0f);
}

__device__ __forceinline__ void mma8(float c[4], uint32_t a0, uint32_t a1,
                                     uint32_t a2, uint32_t a3,
                                     uint32_t b0, uint32_t b1) {
    asm("mma.sync.aligned.m16n8k8.row.col.f32.tf32.tf32.f32 "
        "{%0,%1,%2,%3},{%4,%5,%6,%7},{%8,%9},{%0,%1,%2,%3};"
        : "+f"(c[0]), "+f"(c[1]), "+f"(c[2]), "+f"(c[3])
        : "r"(a0), "r"(a1), "r"(a2), "r"(a3), "r"(b0), "r"(b1));
}

__device__ __forceinline__ void cp16(uint32_t saddr, const float* g) {
    asm volatile("cp.async.cg.shared.global [%0], [%1], 16;" ::"r"(saddr), "l"(g));
}
__device__ __forceinline__ void cpcommit() {
    asm volatile("cp.async.commit_group;" ::: "memory");
}
template <int P>
__device__ __forceinline__ void cpwait() {
    asm volatile("cp.async.wait_group %0;" ::"n"(P) : "memory");
}

// Stage KCH rows of W (K x N, row-major) into a SMEM slot with WSTR stride.
template <int N>
__device__ __forceinline__ void stageW(float* slot, const float* Wg, int kbase) {
    uint32_t sb = (uint32_t)__cvta_generic_to_shared(slot);
    constexpr int OPS = KCH * (N / 4);  // 16B ops; divisible by NTHREADS for N>=64
#pragma unroll
    for (int o = 0; o < OPS / NTHREADS; o++) {
        int idx = o * NTHREADS + (int)threadIdx.x;
        int r = idx / (N / 4);
        int s = idx % (N / 4);
        cp16(sb + (uint32_t)(r * WSTR + s * 4) * 4u, Wg + (kbase + r) * N + s * 4);
    }
}

// C[2][NF][4] = A(64 x K, SMEM Ab) * W(K x N, global pre-rounded).
// Warp grid 2(M) x 8(N); per-warp tile 32 x N/8; NF = N/64.
// 3-slot cp.async pipeline, ONE barrier per chunk + one trailing barrier:
//   slot s read at chunk ch (s=ch%3) is restaged at chunk ch+2, whose stage
//   happens only after that warp passed top-sync of ch+1, which implies ALL
//   warps finished reading chunk ch. The trailing barrier orders the last
//   chunk's reads against the epilogue's Ab writes / next GEMM's staging.
template <int K, int N>
__device__ __forceinline__ void gemm_core(const float* __restrict__ Wg,
                                          const float* __restrict__ Ab,
                                          float* __restrict__ Wb,
                                          float C[2][4][4], int m0, int n0,
                                          int g, int t) {
    constexpr int NF = N / 64;
#pragma unroll
    for (int mi = 0; mi < 2; mi++)
#pragma unroll
        for (int j = 0; j < NF; j++)
#pragma unroll
            for (int e = 0; e < 4; e++) C[mi][j][e] = 0.0f;

    constexpr int NCH = K / KCH;
    stageW<N>(Wb, Wg, 0);
    cpcommit();
    int scur = 0, snxt = 1;
#pragma unroll 1
    for (int ch = 0; ch < NCH; ch++) {
        if (ch + 1 < NCH) {
            stageW<N>(Wb + snxt * (KCH * WSTR), Wg, (ch + 1) * KCH);
            cpcommit();
            cpwait<1>();
        } else {
            cpwait<0>();
        }
        __syncthreads();  // staged chunk visible; orders epilogue Ab writes too
        const float* W = Wb + scur * (KCH * WSTR);
#pragma unroll
        for (int k8 = 0; k8 < KCH / 8; k8++) {
            const int ka = ch * KCH + k8 * 8;
            uint32_t a[2][4];
#pragma unroll
            for (int mi = 0; mi < 2; mi++) {
                const float* Ar0 = Ab + (m0 + mi * 16 + g) * AS + ka;
                const float* Ar1 = Ab + (m0 + mi * 16 + g + 8) * AS + ka;
                a[mi][0] = __float_as_uint(Ar0[t]);
                a[mi][1] = __float_as_uint(Ar1[t]);
                a[mi][2] = __float_as_uint(Ar0[t + 4]);
                a[mi][3] = __float_as_uint(Ar1[t + 4]);
            }
            const float* Wk = W + (k8 * 8) * WSTR;
#pragma unroll
            for (int j = 0; j < NF; j++) {
                uint32_t b0 = __float_as_uint(Wk[t * WSTR + n0 + j * 8 + g]);
                uint32_t b1 = __float_as_uint(Wk[(t + 4) * WSTR + n0 + j * 8 + g]);
                mma8(C[0][j], a[0][0], a[0][1], a[0][2], a[0][3], b0, b1);
                mma8(C[1][j], a[1][0], a[1][1], a[1][2], a[1][3], b0, b1);
            }
        }
        scur = snxt;
        snxt = (snxt == NSLOT - 1) ? 0 : snxt + 1;
    }
    __syncthreads();  // all reads of Ab/last slot done before epilogue/restage
}

__global__ void prep_kernel(const float* We, const float* W1, const float* W2,
                            const float* W3, const float* Wd) {
    int i = blockIdx.x * blockDim.x + threadIdx.x;
    if (i < IN_DIM * HID) g_Wenc[i] = tf32r(We[i]);
    if (i < HID * HID2) g_W1[i] = tf32r(W1[i]);
    if (i < HID2 * HID2) g_W2[i] = tf32r(W2[i]);
    if (i < HID2 * HID) g_W3[i] = tf32r(W3[i]);
    if (i < HID * OUT_DIM) g_Wdec[i] = tf32r(Wd[i]);
}

__global__ void __launch_bounds__(NTHREADS, 1)
node_kernel(const float* __restrict__ x, const float* __restrict__ benc,
            const float* __restrict__ b1, const float* __restrict__ b2,
            const float* __restrict__ b3, const float* __restrict__ bdec,
            float* __restrict__ out) {
    extern __shared__ float smem[];
    float* Ab  = smem;                        // [64][AS]  activations (tf32)
    float* Wb  = Ab + M_TILE * AS;            // [3][KCH][WSTR] weight pipeline
    float* Acc = Wb + NSLOT * KCH * WSTR;     // [64][HS]  RK4 accumulator
    float* Bs  = Acc + M_TILE * HS;           // biases (832 floats)

    const int tid = threadIdx.x;
    if (tid < 256) {
        Bs[tid] = b1[tid];
        Bs[256 + tid] = b2[tid];
    }
    if (tid < 128) {
        Bs[512 + tid] = b3[tid];
        Bs[640 + tid] = benc[tid];
    }
    if (tid < 64) Bs[768 + tid] = bdec[tid];

    const int row0 = blockIdx.x * M_TILE;
#pragma unroll 4
    for (int i = tid; i < M_TILE * IN_DIM; i += NTHREADS) {
        int r = i >> 6, c = i & 63;
        Ab[r * AS + c] = tf32r(x[(row0 + r) * IN_DIM + c]);
    }
    // gemm_core's first top-barrier publishes Ab/Bs to all warps.

    const int warp = tid >> 5, lane = tid & 31;
    const int mw = warp >> 3, nwp = warp & 7;   // 2 x 8 warp grid
    const int g = lane >> 2, t = lane & 3;
    const int m0 = mw * 32;

    float C[2][4][4];
    float hreg[2][2][4];   // h state, GEMM3/encoder C-fragment layout

    // ---- encoder: tanh(x @ Wenc + benc) -> hreg, Ab ----
    {
        const int n0 = nwp * 16;  // NF = 2
        gemm_core<IN_DIM, HID>(g_Wenc, Ab, Wb, C, m0, n0, g, t);
#pragma unroll
        for (int mi = 0; mi < 2; mi++)
#pragma unroll
            for (int j = 0; j < 2; j++)
#pragma unroll
                for (int e = 0; e < 4; e++) {
                    int rr = m0 + mi * 16 + g + ((e >> 1) << 3);
                    int cc = n0 + j * 8 + 2 * t + (e & 1);
                    float v = fast_tanh(C[mi][j][e] + Bs[640 + cc]);
                    hreg[mi][j][e] = v;
                    Ab[rr * AS + cc] = tf32r(v);
                }
    }

#pragma unroll 1
    for (int step = 0; step < NSTEPS; step++) {
#pragma unroll 1
        for (int ev = 0; ev < 4; ev++) {
            // GEMM1: tanh(htmp @ W1 + b1) -> Ab[:, 0:256)
            {
                const int n0 = nwp * 32;  // NF = 4
                gemm_core<HID, HID2>(g_W1, Ab, Wb, C, m0, n0, g, t);
#pragma unroll
                for (int mi = 0; mi < 2; mi++)
#pragma unroll
                    for (int j = 0; j < 4; j++)
#pragma unroll
                        for (int e = 0; e < 4; e++) {
                            int rr = m0 + mi * 16 + g + ((e >> 1) << 3);
                            int cc = n0 + j * 8 + 2 * t + (e & 1);
                            Ab[rr * AS + cc] = tf32r(fast_tanh(C[mi][j][e] + Bs[cc]));
                        }
            }
            // GEMM2: tanh(z1 @ W2 + b2) -> Ab
            {
                const int n0 = nwp * 32;  // NF = 4
                gemm_core<HID2, HID2>(g_W2, Ab, Wb, C, m0, n0, g, t);
#pragma unroll
                for (int mi = 0; mi < 2; mi++)
#pragma unroll
                    for (int j = 0; j < 4; j++)
#pragma unroll
                        for (int e = 0; e < 4; e++) {
                            int rr = m0 + mi * 16 + g + ((e >> 1) << 3);
                            int cc = n0 + j * 8 + 2 * t + (e & 1);
                            Ab[rr * AS + cc] = tf32r(fast_tanh(C[mi][j][e] + Bs[256 + cc]));
                        }
            }
            // GEMM3: k = z2 @ W3 + b3 ; RK4 bookkeeping -> Ab[:, 0:128), hreg
            {
                const int n0 = nwp * 16;  // NF = 2
                gemm_core<HID2, HID>(g_W3, Ab, Wb, C, m0, n0, g, t);
#pragma unroll
                for (int mi = 0; mi < 2; mi++)
#pragma unroll
                    for (int j = 0; j < 2; j++)
#pragma unroll
                        for (int e = 0; e < 4; e++) {
                            int rr = m0 + mi * 16 + g + ((e >> 1) << 3);
                            int cc = n0 + j * 8 + 2 * t + (e & 1);
                            float kv = C[mi][j][e] + Bs[512 + cc];
                            float h = hreg[mi][j][e];
                            float* ap = &Acc[rr * HS + cc];
                            if (ev == 0) {
                                *ap = kv;
                                Ab[rr * AS + cc] = tf32r(fmaf(0.5f * DTC, kv, h));
                            } else if (ev == 1) {
                                *ap += 2.0f * kv;
                                Ab[rr * AS + cc] = tf32r(fmaf(0.5f * DTC, kv, h));
                            } else if (ev == 2) {
                                *ap += 2.0f * kv;
                                Ab[rr * AS + cc] = tf32r(fmaf(DTC, kv, h));
                            } else {
                                float hn = fmaf(DTC / 6.0f, *ap + kv, h);
                                hreg[mi][j][e] = hn;
                                Ab[rr * AS + cc] = tf32r(hn);
                            }
                        }
            }
        }
    }

    // ---- decoder: hT @ Wdec + bdec -> out ----
    {
        const int n0 = nwp * 8;  // NF = 1
        gemm_core<HID, OUT_DIM>(g_Wdec, Ab, Wb, C, m0, n0, g, t);
#pragma unroll
        for (int mi = 0; mi < 2; mi++)
#pragma unroll
            for (int e = 0; e < 4; e++) {
                int rr = m0 + mi * 16 + g + ((e >> 1) << 3);
                int cc = n0 + 2 * t + (e & 1);
                out[(size_t)(row0 + rr) * OUT_DIM + cc] = C[mi][0][e] + Bs[768 + cc];
            }
    }
}

static constexpr int SMEM_BYTES =
    (M_TILE * AS + NSLOT * KCH * WSTR + M_TILE * HS + 832) * 4;  // 205,056 B

extern "C" void kernel_launch(void* const* d_in, const int* in_sizes, int n_in,
                              void* d_out, int out_size) {
    const float* x    = (const float*)d_in[0];
    const float* Wenc = (const float*)d_in[1];
    const float* benc = (const float*)d_in[2];
    const float* W1   = (const float*)d_in[3];
    const float* b1   = (const float*)d_in[4];
    const float* W2   = (const float*)d_in[5];
    const float* b2   = (const float*)d_in[6];
    const float* W3   = (const float*)d_in[7];
    const float* b3   = (const float*)d_in[8];
    const float* Wdec = (const float*)d_in[9];
    const float* bdec = (const float*)d_in[10];
    float* out = (float*)d_out;

    const int batch = in_sizes[0] / IN_DIM;  // 65536
    const int grid  = batch / M_TILE;        // 1024

    cudaFuncSetAttribute(node_kernel, cudaFuncAttributeMaxDynamicSharedMemorySize,
                         SMEM_BYTES);

    prep_kernel<<<256, 256>>>(Wenc, W1, W2, W3, Wdec);
    node_kernel<<<grid, NTHREADS, SMEM_BYTES>>>(x, benc, b1, b2, b3, bdec, out);
}

// round 7
// speedup vs baseline: 1.0786x; 1.0712x over previous
#include <cuda_runtime.h>
#include <cstdint>

#define IN_DIM   64
#define HID      128
#define HID2     256
#define OUT_DIM  64
#define NSTEPS   20
#define NTHREADS 512
#define M_TILE   64
#define KCH      32     // K rows per staged chunk
#define NSLOT    3      // weight pipeline depth
#define SLOTF    8192   // floats per weight slot (max: 2 k16 * 32 n8 * 128)
#define AF_K8    32     // fixed k8 stride in Af (covers K up to 256)
#define HS       132    // acc buffer row stride

static constexpr float DTC = 1.0f / 20.0f;

// Weights pre-packed (TF32-RN) into b-fragment order [k16][N/8][lane(4g+t)][v]
//   v0 = W[16k16+t   ][8j+g], v1 = W[16k16+t+4 ][8j+g],
//   v2 = W[16k16+t+8 ][8j+g], v3 = W[16k16+t+12][8j+g]
__device__ float g_Wenc[IN_DIM * HID];
__device__ float g_W1[HID * HID2];
__device__ float g_W2[HID2 * HID2];
__device__ float g_W3[HID2 * HID];
__device__ float g_Wdec[HID * OUT_DIM];

__device__ __forceinline__ float tf32r(float x) {
    uint32_t u;
    asm("cvt.rna.tf32.f32 %0, %1;" : "=r"(u) : "f"(x));
    return __uint_as_float(u);
}
__device__ __forceinline__ uint32_t fu(float x) { return __float_as_uint(x); }

// tanh(x) = 1 - 2/(e^{2x}+1); MUFU ex2/rcp (~1e-6 err), saturates correctly.
__device__ __forceinline__ float fast_tanh(float x) {
    float e;
    asm("ex2.approx.f32 %0, %1;" : "=f"(e) : "f"(x * 2.88539008177792681472f));
    float r;
    asm("rcp.approx.f32 %0, %1;" : "=f"(r) : "f"(e + 1.0f));
    return fmaf(-2.0f, r, 1.0f);
}

__device__ __forceinline__ void mma8(float c[4], uint32_t a0, uint32_t a1,
                                     uint32_t a2, uint32_t a3,
                                     uint32_t b0, uint32_t b1) {
    asm("mma.sync.aligned.m16n8k8.row.col.f32.tf32.tf32.f32 "
        "{%0,%1,%2,%3},{%4,%5,%6,%7},{%8,%9},{%0,%1,%2,%3};"
        : "+f"(c[0]), "+f"(c[1]), "+f"(c[2]), "+f"(c[3])
        : "r"(a0), "r"(a1), "r"(a2), "r"(a3), "r"(b0), "r"(b1));
}

__device__ __forceinline__ void cp16(uint32_t saddr, const float* g) {
    asm volatile("cp.async.cg.shared.global [%0], [%1], 16;" ::"r"(saddr), "l"(g));
}
__device__ __forceinline__ void cpcommit() {
    asm volatile("cp.async.commit_group;" ::: "memory");
}
template <int P>
__device__ __forceinline__ void cpwait() {
    asm volatile("cp.async.wait_group %0;" ::"n"(P) : "memory");
}

// Stage one chunk (2 k16 blocks, all N) of packed W: pure linear copy.
template <int N>
__device__ __forceinline__ void stageW(float* slot, const float* Wg_chunk) {
    constexpr int OPS = (2 * (N / 8) * 128) / 4;  // 16B ops
    uint32_t sb = (uint32_t)__cvta_generic_to_shared(slot);
#pragma unroll
    for (int o = 0; o < OPS / NTHREADS; o++) {
        int idx = o * NTHREADS + (int)threadIdx.x;
        cp16(sb + (uint32_t)idx * 16u, Wg_chunk + idx * 4);
    }
}

// C[2][NF][4] += A(64 x K, fragment-packed SMEM) * W(K x N, fragment-packed).
// Warp grid 2(M) x 8(N); per-warp tile 32 x N/8; NF = N/64. All LDS are .128.
// 3-slot cp.async pipeline: slot read at chunk ch is restaged at ch+2, which
// stages only after this warp passed the top-sync of ch+1 (=> all warps done
// reading ch). Trailing barrier covers the last chunk + epilogue Af writes.
template <int K, int N>
__device__ __forceinline__ void gemm_core(const float* __restrict__ Wg,
                                          const float* __restrict__ Af,
                                          float* __restrict__ Wb,
                                          float C[2][4][4], int tile0, int nwp,
                                          int lane) {
    constexpr int NF = N / 64;
    constexpr int N8 = N / 8;
    constexpr int SLOT_G = 2 * N8 * 128;  // floats per chunk in global
    constexpr int NCH = K / KCH;
#pragma unroll
    for (int mi = 0; mi < 2; mi++)
#pragma unroll
        for (int j = 0; j < NF; j++)
#pragma unroll
            for (int e = 0; e < 4; e++) C[mi][j][e] = 0.0f;

    stageW<N>(Wb, Wg);
    cpcommit();
    int scur = 0, snxt = 1;
    const float* A0p = Af + (tile0 * AF_K8) * 128 + lane * 4;
    const float* A1p = A0p + AF_K8 * 128;
#pragma unroll 1
    for (int ch = 0; ch < NCH; ch++) {
        if (ch + 1 < NCH) {
            stageW<N>(Wb + snxt * SLOTF, Wg + (ch + 1) * SLOT_G);
            cpcommit();
            cpwait<1>();
        } else {
            cpwait<0>();
        }
        __syncthreads();  // chunk visible; also orders epilogue Af writes
        const float* Ws = Wb + scur * SLOTF + lane * 4;
#pragma unroll
        for (int k16 = 0; k16 < 2; k16++) {
            const int k8 = ch * 4 + k16 * 2;
            float4 a00 = *(const float4*)(A0p + k8 * 128);
            float4 a01 = *(const float4*)(A0p + (k8 + 1) * 128);
            float4 a10 = *(const float4*)(A1p + k8 * 128);
            float4 a11 = *(const float4*)(A1p + (k8 + 1) * 128);
#pragma unroll
            for (int j = 0; j < NF; j++) {
                float4 B = *(const float4*)(Ws + (k16 * N8 + nwp * NF + j) * 128);
                mma8(C[0][j], fu(a00.x), fu(a00.y), fu(a00.z), fu(a00.w), fu(B.x), fu(B.y));
                mma8(C[1][j], fu(a10.x), fu(a10.y), fu(a10.z), fu(a10.w), fu(B.x), fu(B.y));
                mma8(C[0][j], fu(a01.x), fu(a01.y), fu(a01.z), fu(a01.w), fu(B.z), fu(B.w));
                mma8(C[1][j], fu(a11.x), fu(a11.y), fu(a11.z), fu(a11.w), fu(B.z), fu(B.w));
            }
        }
        scur = snxt;
        snxt = (snxt == NSLOT - 1) ? 0 : snxt + 1;
    }
    __syncthreads();  // all reads done before epilogue writes / next staging
}

__device__ __forceinline__ void packW(int i, int K, int N, const float* src,
                                      float* dst) {
    int N8 = N / 8;
    int per_k16 = N8 * 128;
    int k16 = i / per_k16;
    int rem = i - k16 * per_k16;
    int j = rem >> 7;
    int l = rem & 127;
    int v = l & 3, lane = l >> 2;
    int g = lane >> 2, t = lane & 3;
    int k = 16 * k16 + t + 4 * v;
    int n = 8 * j + g;
    dst[i] = tf32r(src[k * N + n]);
}

__global__ void prep_kernel(const float* We, const float* W1, const float* W2,
                            const float* W3, const float* Wd) {
    int i = blockIdx.x * blockDim.x + threadIdx.x;
    if (i < IN_DIM * HID) packW(i, IN_DIM, HID, We, g_Wenc);
    if (i < HID * HID2) packW(i, HID, HID2, W1, g_W1);
    if (i < HID2 * HID2) packW(i, HID2, HID2, W2, g_W2);
    if (i < HID2 * HID) packW(i, HID2, HID, W3, g_W3);
    if (i < HID * OUT_DIM) packW(i, HID, OUT_DIM, Wd, g_Wdec);
}

__global__ void __launch_bounds__(NTHREADS, 1)
node_kernel(const float* __restrict__ x, const float* __restrict__ benc,
            const float* __restrict__ b1, const float* __restrict__ b2,
            const float* __restrict__ b3, const float* __restrict__ bdec,
            float* __restrict__ out) {
    extern __shared__ float smem[];
    float* Af  = smem;                       // [4 tiles][32 k8][128] fragments
    float* Wb  = Af + 4 * AF_K8 * 128;       // [3][SLOTF] weight pipeline
    float* Acc = Wb + NSLOT * SLOTF;         // [64][HS] RK4 accumulator
    float* Bs  = Acc + M_TILE * HS;          // biases (832 floats)

    const int tid = threadIdx.x;
    if (tid < 256) {
        Bs[tid] = b1[tid];
        Bs[256 + tid] = b2[tid];
    }
    if (tid < 128) {
        Bs[512 + tid] = b3[tid];
        Bs[640 + tid] = benc[tid];
    }
    if (tid < 64) Bs[768 + tid] = bdec[tid];

    const int row0 = blockIdx.x * M_TILE;
    // x -> Af fragment layout (once)
#pragma unroll
    for (int s = 0; s < (M_TILE * IN_DIM) / NTHREADS; s++) {
        int i = s * NTHREADS + tid;
        int r = i >> 6, c = i & 63;
        int tile = r >> 4, gg = r & 7, hi = (r & 15) >> 3;
        int k8 = c >> 3, in8 = c & 7;
        int tt = in8 & 3, colhi = in8 >> 2;
        int v = 2 * colhi + hi;
        int ln = 4 * gg + tt;
        Af[((tile * AF_K8 + k8) << 7) + ln * 4 + v] = tf32r(x[(row0 + r) * IN_DIM + c]);
    }
    // first gemm_core's top barrier publishes Af/Bs.

    const int warp = tid >> 5, lane = tid & 31;
    const int mw = warp >> 3, nwp = warp & 7;  // 2 x 8 warp grid
    const int g = lane >> 2, t = lane & 3;
    const int tile0 = mw * 2;

    // epilogue store offset inside a [128]-float fragment block:
    //   pair (e=0,e=2) at epA, pair (e=1,e=3) at epA+4  (float2 each)
    const int epA = (4 * g + 2 * (t & 1)) * 4 + 2 * (t >> 1);

    float C[2][4][4];
    float hreg[2][2][4];  // h state in GEMM3/encoder C-fragment layout

    // ---- encoder: tanh(x @ Wenc + benc) -> hreg, Af[k8 0:16) ----
    {
        const int n0 = nwp * 16;  // NF = 2
        gemm_core<IN_DIM, HID>(g_Wenc, Af, Wb, C, tile0, nwp, lane);
#pragma unroll
        for (int mi = 0; mi < 2; mi++)
#pragma unroll
            for (int j = 0; j < 2; j++) {
                float tmp[4];
#pragma unroll
                for (int e = 0; e < 4; e++) {
                    int cc = n0 + j * 8 + 2 * t + (e & 1);
                    float v = fast_tanh(C[mi][j][e] + Bs[640 + cc]);
                    hreg[mi][j][e] = v;
                    tmp[e] = tf32r(v);
                }
                float* dst = &Af[(((tile0 + mi) * AF_K8 + (n0 >> 3) + j) << 7) + epA];
                *(float2*)dst = make_float2(tmp[0], tmp[2]);
                *(float2*)(dst + 4) = make_float2(tmp[1], tmp[3]);
            }
    }

#pragma unroll 1
    for (int step = 0; step < NSTEPS; step++) {
#pragma unroll 1
        for (int ev = 0; ev < 4; ev++) {
            // GEMM1: tanh(htmp @ W1 + b1) -> Af[k8 0:32)
            {
                const int n0 = nwp * 32;  // NF = 4
                gemm_core<HID, HID2>(g_W1, Af, Wb, C, tile0, nwp, lane);
#pragma unroll
                for (int mi = 0; mi < 2; mi++)
#pragma unroll
                    for (int j = 0; j < 4; j++) {
                        float tmp[4];
#pragma unroll
                        for (int e = 0; e < 4; e++) {
                            int cc = n0 + j * 8 + 2 * t + (e & 1);
                            tmp[e] = tf32r(fast_tanh(C[mi][j][e] + Bs[cc]));
                        }
                        float* dst = &Af[(((tile0 + mi) * AF_K8 + (n0 >> 3) + j) << 7) + epA];
                        *(float2*)dst = make_float2(tmp[0], tmp[2]);
                        *(float2*)(dst + 4) = make_float2(tmp[1], tmp[3]);
                    }
            }
            // GEMM2: tanh(z1 @ W2 + b2) -> Af[k8 0:32)
            {
                const int n0 = nwp * 32;  // NF = 4
                gemm_core<HID2, HID2>(g_W2, Af, Wb, C, tile0, nwp, lane);
#pragma unroll
                for (int mi = 0; mi < 2; mi++)
#pragma unroll
                    for (int j = 0; j < 4; j++) {
                        float tmp[4];
#pragma unroll
                        for (int e = 0; e < 4; e++) {
                            int cc = n0 + j * 8 + 2 * t + (e & 1);
                            tmp[e] = tf32r(fast_tanh(C[mi][j][e] + Bs[256 + cc]));
                        }
                        float* dst = &Af[(((tile0 + mi) * AF_K8 + (n0 >> 3) + j) << 7) + epA];
                        *(float2*)dst = make_float2(tmp[0], tmp[2]);
                        *(float2*)(dst + 4) = make_float2(tmp[1], tmp[3]);
                    }
            }
            // GEMM3: k = z2 @ W3 + b3 ; RK4 -> Af[k8 0:16), hreg
            {
                const int n0 = nwp * 16;  // NF = 2
                gemm_core<HID2, HID>(g_W3, Af, Wb, C, tile0, nwp, lane);
#pragma unroll
                for (int mi = 0; mi < 2; mi++)
#pragma unroll
                    for (int j = 0; j < 2; j++) {
                        float tmp[4];
#pragma unroll
                        for (int e = 0; e < 4; e++) {
                            int cc = n0 + j * 8 + 2 * t + (e & 1);
                            int rr = (tile0 + mi) * 16 + g + 8 * (e >> 1);
                            float kv = C[mi][j][e] + Bs[512 + cc];
                            float h = hreg[mi][j][e];
                            float* ap = &Acc[rr * HS + cc];
                            float av;
                            if (ev == 0) {
                                *ap = kv;
                                av = fmaf(0.5f * DTC, kv, h);
                            } else if (ev == 1) {
                                *ap += 2.0f * kv;
                                av = fmaf(0.5f * DTC, kv, h);
                            } else if (ev == 2) {
                                *ap += 2.0f * kv;
                                av = fmaf(DTC, kv, h);
                            } else {
                                av = fmaf(DTC / 6.0f, *ap + kv, h);
                                hreg[mi][j][e] = av;
                            }
                            tmp[e] = tf32r(av);
                        }
                        float* dst = &Af[(((tile0 + mi) * AF_K8 + (n0 >> 3) + j) << 7) + epA];
                        *(float2*)dst = make_float2(tmp[0], tmp[2]);
                        *(float2*)(dst + 4) = make_float2(tmp[1], tmp[3]);
                    }
            }
        }
    }

    // ---- decoder: hT @ Wdec + bdec -> out ----
    {
        const int n0 = nwp * 8;  // NF = 1
        gemm_core<HID, OUT_DIM>(g_Wdec, Af, Wb, C, tile0, nwp, lane);
#pragma unroll
        for (int mi = 0; mi < 2; mi++) {
            int rr0 = (tile0 + mi) * 16 + g;
            float2 o0 = make_float2(C[mi][0][0] + Bs[768 + n0 + 2 * t],
                                    C[mi][0][1] + Bs[768 + n0 + 2 * t + 1]);
            float2 o1 = make_float2(C[mi][0][2] + Bs[768 + n0 + 2 * t],
                                    C[mi][0][3] + Bs[768 + n0 + 2 * t + 1]);
            *(float2*)&out[(size_t)(row0 + rr0) * OUT_DIM + n0 + 2 * t] = o0;
            *(float2*)&out[(size_t)(row0 + rr0 + 8) * OUT_DIM + n0 + 2 * t] = o1;
        }
    }
}

static constexpr int SMEM_BYTES =
    (4 * AF_K8 * 128 + NSLOT * SLOTF + M_TILE * HS + 832) * 4;  // 200,960 B

extern "C" void kernel_launch(void* const* d_in, const int* in_sizes, int n_in,
                              void* d_out, int out_size) {
    const float* x    = (const float*)d_in[0];
    const float* Wenc = (const float*)d_in[1];
    const float* benc = (const float*)d_in[2];
    const float* W1   = (const float*)d_in[3];
    const float* b1   = (const float*)d_in[4];
    const float* W2   = (const float*)d_in[5];
    const float* b2   = (const float*)d_in[6];
    const float* W3   = (const float*)d_in[7];
    const float* b3   = (const float*)d_in[8];
    const float* Wdec = (const float*)d_in[9];
    const float* bdec = (const float*)d_in[10];
    float* out = (float*)d_out;

    const int batch = in_sizes[0] / IN_DIM;  // 65536
    const int grid  = batch / M_TILE;        // 1024

    cudaFuncSetAttribute(node_kernel, cudaFuncAttributeMaxDynamicSharedMemorySize,
                         SMEM_BYTES);

    prep_kernel<<<256, 256>>>(Wenc, W1, W2, W3, Wdec);
    node_kernel<<<grid, NTHREADS, SMEM_BYTES>>>(x, benc, b1, b2, b3, bdec, out);
}